// round 9
// baseline (speedup 1.0000x reference)
#include <cuda_runtime.h>

#define BDIM 8
#define NDIM 2048
#define DDIM 512
#define P_ASEM 0.6f

// Scratch: esi[b*N+i] = exp(-(si+bias)), esj[b*N+j] = exp(-sj)
__device__ float g_esi[BDIM * NDIM];
__device__ float g_esj[BDIM * NDIM];

// Kernel 1: one warp per 2 rows (measured optimum). 8 x-loads in flight/lane.
__global__ void row_dots_kernel(const float* __restrict__ x,
                                const float* __restrict__ W,
                                const float* __restrict__ bias) {
    int warp_id = (blockIdx.x * blockDim.x + threadIdx.x) >> 5;
    int lane = threadIdx.x & 31;
    int row0 = warp_id * 2;
    if (row0 >= BDIM * NDIM) return;

    const float4* xr0 = reinterpret_cast<const float4*>(x + (size_t)row0 * DDIM);
    const float4* xr1 = xr0 + (DDIM / 4);
    const float4* Wi = reinterpret_cast<const float4*>(W);
    const float4* Wj = reinterpret_cast<const float4*>(W + DDIM);

    float si0 = 0.f, sj0 = 0.f, si1 = 0.f, sj1 = 0.f;
#pragma unroll
    for (int k = 0; k < DDIM / 4 / 32; k++) {
        int d4 = lane + k * 32;
        float4 x0 = __ldcs(xr0 + d4);
        float4 x1 = __ldcs(xr1 + d4);
        float4 wi = Wi[d4];
        float4 wj = Wj[d4];
        si0 += x0.x * wi.x + x0.y * wi.y + x0.z * wi.z + x0.w * wi.w;
        sj0 += x0.x * wj.x + x0.y * wj.y + x0.z * wj.z + x0.w * wj.w;
        si1 += x1.x * wi.x + x1.y * wi.y + x1.z * wi.z + x1.w * wi.w;
        sj1 += x1.x * wj.x + x1.y * wj.y + x1.z * wj.z + x1.w * wj.w;
    }
#pragma unroll
    for (int o = 16; o; o >>= 1) {
        si0 += __shfl_down_sync(0xffffffffu, si0, o);
        sj0 += __shfl_down_sync(0xffffffffu, sj0, o);
        si1 += __shfl_down_sync(0xffffffffu, si1, o);
        sj1 += __shfl_down_sync(0xffffffffu, sj1, o);
    }
    if (lane == 0) {
        float b0 = bias[0];
        g_esi[row0]     = __expf(-(si0 + b0));
        g_esj[row0]     = __expf(-sj0);
        g_esi[row0 + 1] = __expf(-(si1 + b0));
        g_esj[row0 + 1] = __expf(-sj1);
    }
}

__device__ __forceinline__ float blend(float esi, float esj, float a) {
    // P * sigmoid(si+sj) + (1-P)*a, with sigmoid = 1/(1+esi*esj)
    return fmaf(P_ASEM, __frcp_rn(fmaf(esi, esj, 1.0f)), (1.0f - P_ASEM) * a);
}

// Kernel 2 (measured optimum): one block per 2 consecutive rows (same batch).
// esj float4s loaded once serve both rows; 4 adj loads front-batched.
__global__ void __launch_bounds__(256) fuse_kernel(const float* __restrict__ adj,
                                                   float* __restrict__ out) {
    unsigned row0 = blockIdx.x * 2u;         // b*2048 + i, i even
    unsigned b_base = row0 & ~(NDIM - 1u);   // b*2048
    unsigned tid = threadIdx.x;

    float esi0 = g_esi[row0];
    float esi1 = g_esi[row0 + 1];

    const float4* adj0 = reinterpret_cast<const float4*>(adj) + (size_t)row0 * (NDIM / 4);
    const float4* adj1 = adj0 + (NDIM / 4);
    float4* out0 = reinterpret_cast<float4*>(out) + (size_t)row0 * (NDIM / 4);
    float4* out1 = out0 + (NDIM / 4);
    const float4* esj_row = reinterpret_cast<const float4*>(g_esj + b_base);

    // front-batched: 4 adj + 2 esj loads in flight
    float4 a00 = __ldcs(adj0 + tid);
    float4 a01 = __ldcs(adj0 + tid + 256);
    float4 a10 = __ldcs(adj1 + tid);
    float4 a11 = __ldcs(adj1 + tid + 256);
    float4 e0 = esj_row[tid];
    float4 e1 = esj_row[tid + 256];

    float4 o;
    o.x = blend(esi0, e0.x, a00.x);
    o.y = blend(esi0, e0.y, a00.y);
    o.z = blend(esi0, e0.z, a00.z);
    o.w = blend(esi0, e0.w, a00.w);
    __stcs(out0 + tid, o);

    o.x = blend(esi0, e1.x, a01.x);
    o.y = blend(esi0, e1.y, a01.y);
    o.z = blend(esi0, e1.z, a01.z);
    o.w = blend(esi0, e1.w, a01.w);
    __stcs(out0 + tid + 256, o);

    o.x = blend(esi1, e0.x, a10.x);
    o.y = blend(esi1, e0.y, a10.y);
    o.z = blend(esi1, e0.z, a10.z);
    o.w = blend(esi1, e0.w, a10.w);
    __stcs(out1 + tid, o);

    o.x = blend(esi1, e1.x, a11.x);
    o.y = blend(esi1, e1.y, a11.y);
    o.z = blend(esi1, e1.z, a11.z);
    o.w = blend(esi1, e1.w, a11.w);
    __stcs(out1 + tid + 256, o);
}

extern "C" void kernel_launch(void* const* d_in, const int* in_sizes, int n_in,
                              void* d_out, int out_size) {
    const float* x   = (const float*)d_in[0];  // (8, 2048, 512)
    const float* adj = (const float*)d_in[1];  // (8, 2048, 2048)
    const float* W   = (const float*)d_in[2];  // (1, 1024)
    const float* b   = (const float*)d_in[3];  // (1,)
    float* out = (float*)d_out;

    // Kernel 1: 16384 rows, 2 rows/warp, 8 warps/block -> 1024 blocks
    row_dots_kernel<<<1024, 256>>>(x, W, b);
    // Kernel 2: 2 rows per block -> 8192 blocks
    fuse_kernel<<<BDIM * NDIM / 2, 256>>>(adj, out);
}

// round 10
// speedup vs baseline: 1.0566x; 1.0566x over previous
#include <cuda_runtime.h>

#define BDIM 8
#define NDIM 2048
#define DDIM 512
#define P_ASEM 0.6f

// Scratch: esi[b*N+i] = exp(-(si+bias)), esj[b*N+j] = exp(-sj)
__device__ float g_esi[BDIM * NDIM];
__device__ float g_esj[BDIM * NDIM];

// Kernel 1: one warp per 2 rows, PLAIN loads (measured optimum — __ldcs here
// regressed non-fuse time 10.5 -> 15.0 us in R9).
__global__ void row_dots_kernel(const float* __restrict__ x,
                                const float* __restrict__ W,
                                const float* __restrict__ bias) {
    int warp_id = (blockIdx.x * blockDim.x + threadIdx.x) >> 5;
    int lane = threadIdx.x & 31;
    int row0 = warp_id * 2;
    if (row0 >= BDIM * NDIM) return;

    const float4* xr0 = reinterpret_cast<const float4*>(x + (size_t)row0 * DDIM);
    const float4* xr1 = xr0 + (DDIM / 4);
    const float4* Wi = reinterpret_cast<const float4*>(W);
    const float4* Wj = reinterpret_cast<const float4*>(W + DDIM);

    float si0 = 0.f, sj0 = 0.f, si1 = 0.f, sj1 = 0.f;
#pragma unroll
    for (int k = 0; k < DDIM / 4 / 32; k++) {
        int d4 = lane + k * 32;
        float4 x0 = xr0[d4];
        float4 x1 = xr1[d4];
        float4 wi = Wi[d4];
        float4 wj = Wj[d4];
        si0 += x0.x * wi.x + x0.y * wi.y + x0.z * wi.z + x0.w * wi.w;
        sj0 += x0.x * wj.x + x0.y * wj.y + x0.z * wj.z + x0.w * wj.w;
        si1 += x1.x * wi.x + x1.y * wi.y + x1.z * wi.z + x1.w * wi.w;
        sj1 += x1.x * wj.x + x1.y * wj.y + x1.z * wj.z + x1.w * wj.w;
    }
#pragma unroll
    for (int o = 16; o; o >>= 1) {
        si0 += __shfl_down_sync(0xffffffffu, si0, o);
        sj0 += __shfl_down_sync(0xffffffffu, sj0, o);
        si1 += __shfl_down_sync(0xffffffffu, si1, o);
        sj1 += __shfl_down_sync(0xffffffffu, sj1, o);
    }
    if (lane == 0) {
        float b0 = bias[0];
        g_esi[row0]     = __expf(-(si0 + b0));
        g_esj[row0]     = __expf(-sj0);
        g_esi[row0 + 1] = __expf(-(si1 + b0));
        g_esj[row0 + 1] = __expf(-sj1);
    }
}

__device__ __forceinline__ float blend(float esi, float esj, float a) {
    // P * sigmoid(si+sj) + (1-P)*a, with sigmoid = 1/(1+esi*esj)
    return fmaf(P_ASEM, __frcp_rn(fmaf(esi, esj, 1.0f)), (1.0f - P_ASEM) * a);
}

// Kernel 2 (measured optimum): one block per 2 consecutive rows (same batch).
// esj float4s loaded once serve both rows; 4 adj loads front-batched;
// streaming hints on the 268MB adj/out streams only.
__global__ void __launch_bounds__(256) fuse_kernel(const float* __restrict__ adj,
                                                   float* __restrict__ out) {
    unsigned row0 = blockIdx.x * 2u;         // b*2048 + i, i even
    unsigned b_base = row0 & ~(NDIM - 1u);   // b*2048
    unsigned tid = threadIdx.x;

    float esi0 = g_esi[row0];
    float esi1 = g_esi[row0 + 1];

    const float4* adj0 = reinterpret_cast<const float4*>(adj) + (size_t)row0 * (NDIM / 4);
    const float4* adj1 = adj0 + (NDIM / 4);
    float4* out0 = reinterpret_cast<float4*>(out) + (size_t)row0 * (NDIM / 4);
    float4* out1 = out0 + (NDIM / 4);
    const float4* esj_row = reinterpret_cast<const float4*>(g_esj + b_base);

    // front-batched: 4 adj + 2 esj loads in flight
    float4 a00 = __ldcs(adj0 + tid);
    float4 a01 = __ldcs(adj0 + tid + 256);
    float4 a10 = __ldcs(adj1 + tid);
    float4 a11 = __ldcs(adj1 + tid + 256);
    float4 e0 = esj_row[tid];
    float4 e1 = esj_row[tid + 256];

    float4 o;
    o.x = blend(esi0, e0.x, a00.x);
    o.y = blend(esi0, e0.y, a00.y);
    o.z = blend(esi0, e0.z, a00.z);
    o.w = blend(esi0, e0.w, a00.w);
    __stcs(out0 + tid, o);

    o.x = blend(esi0, e1.x, a01.x);
    o.y = blend(esi0, e1.y, a01.y);
    o.z = blend(esi0, e1.z, a01.z);
    o.w = blend(esi0, e1.w, a01.w);
    __stcs(out0 + tid + 256, o);

    o.x = blend(esi1, e0.x, a10.x);
    o.y = blend(esi1, e0.y, a10.y);
    o.z = blend(esi1, e0.z, a10.z);
    o.w = blend(esi1, e0.w, a10.w);
    __stcs(out1 + tid, o);

    o.x = blend(esi1, e1.x, a11.x);
    o.y = blend(esi1, e1.y, a11.y);
    o.z = blend(esi1, e1.z, a11.z);
    o.w = blend(esi1, e1.w, a11.w);
    __stcs(out1 + tid + 256, o);
}

extern "C" void kernel_launch(void* const* d_in, const int* in_sizes, int n_in,
                              void* d_out, int out_size) {
    const float* x   = (const float*)d_in[0];  // (8, 2048, 512)
    const float* adj = (const float*)d_in[1];  // (8, 2048, 2048)
    const float* W   = (const float*)d_in[2];  // (1, 1024)
    const float* b   = (const float*)d_in[3];  // (1,)
    float* out = (float*)d_out;

    // Kernel 1: 16384 rows, 2 rows/warp, 8 warps/block -> 1024 blocks
    row_dots_kernel<<<1024, 256>>>(x, W, b);
    // Kernel 2: 2 rows per block -> 8192 blocks
    fuse_kernel<<<BDIM * NDIM / 2, 256>>>(adj, out);
}